// round 4
// baseline (speedup 1.0000x reference)
#include <cuda_runtime.h>
#include <math.h>

#define T_STEPS 1024
#define BATCH   64
#define DIM     256
#define NCTA    64

// ---- scratch (static __device__ arrays: allocation-free) ----
__device__ float g_Xz[T_STEPS * BATCH * DIM];
__device__ float g_Xr[T_STEPS * BATCH * DIM];
__device__ float g_Xh[T_STEPS * BATCH * DIM];
__device__ float g_h[BATCH * DIM];
__device__ float g_rh[BATCH * DIM];
__device__ unsigned g_bar;

__global__ void reset_kernel() { g_bar = 0u; }

// ============================================================
// Kernel A: X @ Wg + bg for g in {z, r, h}.
// Output layout permuted for the recurrent kernel:
//   Xg[((t*64 + n/4)*64 + b)*4 + (n%3... n&3)]
// so CTA cb's per-step reads are one fully-coalesced 128B line per warp.
// Block tile 64 rows (= one t) x 64 cols, 256 threads, 4x4 per thread.
// ============================================================
__global__ __launch_bounds__(256) void x_proj_kernel(
    const float* __restrict__ X,
    const float* __restrict__ Wz, const float* __restrict__ Wr, const float* __restrict__ Wh,
    const float* __restrict__ bz, const float* __restrict__ br, const float* __restrict__ bh)
{
    const float* W; const float* bias; float* out;
    if (blockIdx.z == 0)      { W = Wz; bias = bz; out = g_Xz; }
    else if (blockIdx.z == 1) { W = Wr; bias = br; out = g_Xr; }
    else                      { W = Wh; bias = bh; out = g_Xh; }

    __shared__ __align__(16) float As[32][68];  // transposed X tile: As[k][row]
    __shared__ __align__(16) float Ws[32][68];  // W tile: Ws[k][col]

    const int tid = threadIdx.x;
    const int tx = tid & 15;          // 0..15 -> 4 cols each
    const int ty = tid >> 4;          // 0..15 -> 4 rows each
    const int t = blockIdx.x;         // row block == one timestep (64 rows)
    const int col0 = blockIdx.y * 64;

    float acc[4][4];
#pragma unroll
    for (int i = 0; i < 4; i++)
#pragma unroll
        for (int j = 0; j < 4; j++) acc[i][j] = 0.0f;

    for (int kk = 0; kk < DIM; kk += 32) {
        // load X tile (transposed into As[k][row])
#pragma unroll
        for (int li = 0; li < 2; li++) {
            int idx = li * 256 + tid;          // 0..511
            int r = idx >> 3;                  // 0..63
            int q = idx & 7;                   // float4 index within 32-k chunk
            float4 v = *(const float4*)&X[(t * 64 + r) * DIM + kk + q * 4];
            As[q * 4 + 0][r] = v.x;
            As[q * 4 + 1][r] = v.y;
            As[q * 4 + 2][r] = v.z;
            As[q * 4 + 3][r] = v.w;
        }
        // load W tile
#pragma unroll
        for (int li = 0; li < 2; li++) {
            int idx = li * 256 + tid;
            int k = idx >> 4;                  // 0..31
            int q = idx & 15;                  // float4 col index
            float4 v = *(const float4*)&W[(kk + k) * DIM + col0 + q * 4];
            *(float4*)&Ws[k][q * 4] = v;
        }
        __syncthreads();
#pragma unroll 8
        for (int k = 0; k < 32; k++) {
            float4 a = *(const float4*)&As[k][ty * 4];
            float4 w = *(const float4*)&Ws[k][tx * 4];
            float av[4] = {a.x, a.y, a.z, a.w};
            float wv[4] = {w.x, w.y, w.z, w.w};
#pragma unroll
            for (int i = 0; i < 4; i++)
#pragma unroll
                for (int j = 0; j < 4; j++)
                    acc[i][j] = fmaf(av[i], wv[j], acc[i][j]);
        }
        __syncthreads();
    }

    float4 bias4 = __ldg((const float4*)&bias[col0 + tx * 4]);
    const int nb = (col0 >> 2) + tx;
#pragma unroll
    for (int i = 0; i < 4; i++) {
        int bb = ty * 4 + i;
        float4 v = make_float4(acc[i][0] + bias4.x, acc[i][1] + bias4.y,
                               acc[i][2] + bias4.z, acc[i][3] + bias4.w);
        *(float4*)&out[((t * 64 + nb) * 64 + bb) * 4] = v;
    }
}

// ============================================================
// Kernel B: persistent recurrence. 64 CTAs x 256 threads.
// CTA cb owns output columns [cb*4, cb*4+4). Thread: b = tid>>2, nl = tid&3.
// Per step: phase1 (z, r gates + write r*h), grid barrier,
//           phase2 (h_bar gate + combine + write new h), grid barrier.
// h / rh exchanged via __device__ globals, read with __ldcg (L2-coherent).
// ============================================================
#define GRID_BARRIER()                                            \
    do {                                                          \
        __threadfence();                                          \
        __syncthreads();                                          \
        bars++;                                                   \
        if (tid == 0) {                                           \
            atomicAdd(&g_bar, 1u);                                \
            unsigned target = bars * (unsigned)NCTA;              \
            while (*(volatile unsigned*)&g_bar < target) { }      \
        }                                                         \
        __syncthreads();                                          \
    } while (0)

__global__ __launch_bounds__(256) void gru_rec_kernel(
    const float* __restrict__ Uh, const float* __restrict__ Ur,
    const float* __restrict__ Uz, const float* __restrict__ h0,
    float* __restrict__ out)
{
    extern __shared__ float smem[];
    float* hs = smem;                 // 64 rows x 260 (padded) floats = 66560B
    float* us = smem + 64 * 260;      // U slices transposed: [z|r|h] x [4][256]

    const int tid = threadIdx.x;
    const int cb = blockIdx.x;        // 0..63
    const int b  = tid >> 2;          // 0..63
    const int nl = tid & 3;           // 0..3
    const int n  = cb * 4 + nl;

    // load this CTA's U column slices, transposed (us[g][nl][k] = Ug[k][n])
    for (int i = tid; i < 1024; i += 256) {
        int nn = i >> 8, k = i & 255;
        int gcol = cb * 4 + nn;
        us[i]        = __ldg(&Uz[k * DIM + gcol]);
        us[1024 + i] = __ldg(&Ur[k * DIM + gcol]);
        us[2048 + i] = __ldg(&Uh[k * DIM + gcol]);
    }

    float h_own = __ldg(&h0[n]);      // init_hidden broadcast over batch
    g_h[b * DIM + n] = h_own;

    unsigned bars = 0;
    GRID_BARRIER();                   // init h visible everywhere; us loaded

    const float4* hrow = (const float4*)(hs + b * 260);   // 65 float4/row
    const float4* uz4  = (const float4*)(us + nl * 256);
    const float4* ur4  = (const float4*)(us + 1024 + nl * 256);
    const float4* uh4  = (const float4*)(us + 2048 + nl * 256);
    const float4* gh4  = (const float4*)g_h;
    const float4* grh4 = (const float4*)g_rh;

    for (int t = 0; t < T_STEPS; t++) {
        // prefetch this step's x-projection values (coalesced 128B/warp)
        int xidx = ((t * 64 + cb) * 64 + b) * 4 + nl;
        float xz = __ldg(&g_Xz[xidx]);
        float xr = __ldg(&g_Xr[xidx]);
        float xh = __ldg(&g_Xh[xidx]);

        // emit PRE-update hidden (reference semantics)
        out[(t * BATCH + b) * DIM + n] = h_own;

        // ---- phase 1: load full h into smem, compute z & r for own cols ----
#pragma unroll
        for (int i = 0; i < 16; i++) {
            int idx = i * 256 + tid;            // 0..4095 float4s
            int r = idx >> 6, c = idx & 63;
            float4 v = __ldcg(gh4 + idx);
            *((float4*)(hs + r * 260) + c) = v;
        }
        __syncthreads();

        float az0 = xz, az1 = 0.0f, ar0 = xr, ar1 = 0.0f;
#pragma unroll 8
        for (int k4 = 0; k4 < 64; k4++) {
            float4 hv = hrow[k4];
            float4 a  = uz4[k4];
            float4 c  = ur4[k4];
            az0 = fmaf(hv.x, a.x, az0); az1 = fmaf(hv.y, a.y, az1);
            az0 = fmaf(hv.z, a.z, az0); az1 = fmaf(hv.w, a.w, az1);
            ar0 = fmaf(hv.x, c.x, ar0); ar1 = fmaf(hv.y, c.y, ar1);
            ar0 = fmaf(hv.z, c.z, ar0); ar1 = fmaf(hv.w, c.w, ar1);
        }
        float az = az0 + az1, ar = ar0 + ar1;
        float z = 1.0f / (1.0f + __expf(-az));
        float r = 1.0f / (1.0f + __expf(-ar));
        g_rh[b * DIM + n] = r * h_own;
        GRID_BARRIER();

        // ---- phase 2: load full r*h, compute h_bar, combine ----
#pragma unroll
        for (int i = 0; i < 16; i++) {
            int idx = i * 256 + tid;
            int rr = idx >> 6, c = idx & 63;
            float4 v = __ldcg(grh4 + idx);
            *((float4*)(hs + rr * 260) + c) = v;
        }
        __syncthreads();

        float ah0 = xh, ah1 = 0.0f;
#pragma unroll 8
        for (int k4 = 0; k4 < 64; k4++) {
            float4 hv = hrow[k4];
            float4 a  = uh4[k4];
            ah0 = fmaf(hv.x, a.x, ah0); ah1 = fmaf(hv.y, a.y, ah1);
            ah0 = fmaf(hv.z, a.z, ah0); ah1 = fmaf(hv.w, a.w, ah1);
        }
        float ah = ah0 + ah1;
        ah = fminf(fmaxf(ah, -20.0f), 20.0f);     // avoid inf/inf -> NaN
        float e = __expf(-2.0f * ah);
        float hbar = (1.0f - e) / (1.0f + e);     // tanh(ah)

        float hnew = (1.0f - r) * h_own + z * hbar;   // note: (1-r), per reference
        h_own = hnew;
        g_h[b * DIM + n] = hnew;
        GRID_BARRIER();
    }
}

extern "C" void kernel_launch(void* const* d_in, const int* in_sizes, int n_in,
                              void* d_out, int out_size)
{
    const float* X   = (const float*)d_in[0];
    const float* W   = (const float*)d_in[1];
    const float* U   = (const float*)d_in[2];
    const float* bh  = (const float*)d_in[3];
    const float* W_r = (const float*)d_in[4];
    const float* U_r = (const float*)d_in[5];
    const float* b_r = (const float*)d_in[6];
    const float* W_z = (const float*)d_in[7];
    const float* U_z = (const float*)d_in[8];
    const float* b_z = (const float*)d_in[9];
    const float* h0  = (const float*)d_in[10];
    float* out = (float*)d_out;

    const int rec_smem = (64 * 260 + 3 * 1024) * (int)sizeof(float);  // 78848 B
    cudaFuncSetAttribute(gru_rec_kernel,
                         cudaFuncAttributeMaxDynamicSharedMemorySize, rec_smem);

    reset_kernel<<<1, 1>>>();
    x_proj_kernel<<<dim3(T_STEPS, 4, 3), 256>>>(X, W_z, W_r, W, b_z, b_r, bh);
    gru_rec_kernel<<<NCTA, 256, rec_smem>>>(U, U_r, U_z, h0, out);
}